// round 11
// baseline (speedup 1.0000x reference)
#include <cuda_runtime.h>

#define NB 256
#define NC 50000
#define ND 512
#define ALPHA_F 0.5f

#define FIND_BLOCKS 3125
#define COPY_BLOCKS 12500
#define WORK_BLOCKS (FIND_BLOCKS + COPY_BLOCKS)   // 15625
#define TAIL_BLOCKS 256
#define GRID_TOTAL  (WORK_BLOCKS + TAIL_BLOCKS)   // 15881

__device__ int g_labels[NB];
// counters are zero at process start and reset to zero by the last tail block
// of every launch -> identical state each replay (deterministic).
__device__ int g_find;
__device__ int g_copy;
__device__ int g_tail;

__global__ __launch_bounds__(256) void k_all(const float4* __restrict__ oh,
                                             const float4* __restrict__ centers,
                                             float4* __restrict__ out,
                                             const float* __restrict__ x,
                                             float* __restrict__ result) {
    int bid = blockIdx.x;
    int t = threadIdx.x;

    if (bid < WORK_BLOCKS) {
        int g = bid / 5;
        int r = bid - g * 5;
        if (r < 4) {
            // ---------------- copy: 512 float4 (4 rows). centers cacheable, out streamed.
            int i = (g * 4 + r) * 512 + t;
            float4 a = __ldg(centers + i);
            float4 b = __ldg(centers + i + 256);
            __stcs(out + i, a);
            __stcs(out + i + 256, b);
            __threadfence();
            __syncthreads();
            if (t == 0) atomicAdd(&g_copy, 1);
        } else {
            // ---------------- find: 1024 float4 of onehot, read-once.
            int base = g * 1024 + t;
            float4 v0 = __ldcs(oh + base);
            float4 v1 = __ldcs(oh + base + 256);
            float4 v2 = __ldcs(oh + base + 512);
            float4 v3 = __ldcs(oh + base + 768);
            #pragma unroll
            for (int k = 0; k < 4; k++) {
                float4 w = (k == 0) ? v0 : (k == 1) ? v1 : (k == 2) ? v2 : v3;
                if (w.x != 0.0f || w.y != 0.0f || w.z != 0.0f || w.w != 0.0f) {
                    int i = base + k * 256;
                    int b = i / (NC / 4);
                    int cb = (i - b * (NC / 4)) * 4;
                    int off = (w.x != 0.0f) ? 0 : (w.y != 0.0f) ? 1 : (w.z != 0.0f) ? 2 : 3;
                    g_labels[b] = cb + off;          // unique writer per sample
                }
            }
            __threadfence();
            __syncthreads();
            if (t == 0) atomicAdd(&g_find, 1);
        }
        return;
    }

    // ======================= tail block: distance + fixup for sample b
    int b = bid - WORK_BLOCKS;
    __shared__ int      s_lab[NB];
    __shared__ unsigned s_mask[8];
    __shared__ float    s_warp[4];

    // ---- phase 1: wait for labels (overlaps with copy stream)
    if (t == 0) {
        while (*(volatile int*)&g_find < FIND_BLOCKS) __nanosleep(32);
        __threadfence();
    }
    __syncthreads();

    s_lab[t] = g_labels[t];
    __syncthreads();
    int lab = s_lab[b];

    unsigned m = __ballot_sync(0xFFFFFFFFu, s_lab[t] == lab);
    if ((t & 31) == 0) s_mask[t >> 5] = m;

    // ---- distance vs OLD centers (128 working threads, float4)
    float s = 0.0f;
    float4 cv = make_float4(0.f, 0.f, 0.f, 0.f);
    if (t < 128) {
        float4 xv = ((const float4*)(x + (size_t)b * ND))[t];
        cv = ((const float4*)((const float*)centers + (size_t)lab * ND))[t];
        float dx = xv.x - cv.x, dy = xv.y - cv.y, dz = xv.z - cv.z, dw = xv.w - cv.w;
        s = dx * dx + dy * dy + dz * dz + dw * dw;
    }
    #pragma unroll
    for (int off = 16; off > 0; off >>= 1)
        s += __shfl_down_sync(0xFFFFFFFFu, s, off);
    if ((t & 31) == 0 && t < 128) s_warp[t >> 5] = s;
    __syncthreads();                                   // covers s_warp + s_mask
    if (t == 0)
        result[b] = s_warp[0] + s_warp[1] + s_warp[2] + s_warp[3];

    // ---- ownership: first sample with this label does the row fixup
    int minidx = NB;
    #pragma unroll
    for (int i = 0; i < 8; i++) {
        unsigned mm = s_mask[i];
        if (mm) { minidx = i * 32 + __ffs(mm) - 1; break; }
    }
    bool owner = (minidx == b);

    // ---- precompute fixup row while copies still stream (latency hidden)
    float4 o = make_float4(0.f, 0.f, 0.f, 0.f);
    if (owner && t < 128) {
        int cnt = 0;
        #pragma unroll
        for (int i = 0; i < 8; i++) cnt += __popc(s_mask[i]);
        float4 sum = make_float4(0.f, 0.f, 0.f, 0.f);
        #pragma unroll
        for (int i = 0; i < 8; i++) {
            unsigned mm = s_mask[i];
            while (mm) {
                int q = i * 32 + __ffs(mm) - 1;       // increasing q: deterministic
                mm &= mm - 1;
                float4 v = ((const float4*)(x + (size_t)q * ND))[t];
                sum.x += v.x; sum.y += v.y; sum.z += v.z; sum.w += v.w;
            }
        }
        float fc = (float)cnt;
        float inv = ALPHA_F / (fc + 1.0f);
        float scale = 1.0f - inv * fc;
        o.x = cv.x * scale + inv * sum.x;
        o.y = cv.y * scale + inv * sum.y;
        o.z = cv.z * scale + inv * sum.z;
        o.w = cv.w * scale + inv * sum.w;
    }

    // ---- phase 2: wait for all copies, then overwrite the touched row
    if (t == 0) {
        while (*(volatile int*)&g_copy < COPY_BLOCKS) __nanosleep(64);
        __threadfence();
    }
    __syncthreads();
    if (owner && t < 128)
        ((float4*)((float*)out + (size_t)lab * ND))[t] = o;

    // ---- reset counters for the next graph replay (last tail block)
    __threadfence();
    __syncthreads();
    if (t == 0) {
        int d = atomicAdd(&g_tail, 1);
        if (d == TAIL_BLOCKS - 1) {
            g_find = 0;
            g_copy = 0;
            g_tail = 0;
        }
    }
}

// ---------------------------------------------------------------- launch
extern "C" void kernel_launch(void* const* d_in, const int* in_sizes, int n_in,
                              void* d_out, int out_size) {
    const float* x       = (const float*)d_in[0];   // [256, 512]
    const float* onehot  = (const float*)d_in[1];   // [256, 50000]
    const float* centers = (const float*)d_in[2];   // [50000, 512]

    float* result      = (float*)d_out;             // [256]
    float* new_centers = (float*)d_out + NB;        // [50000, 512]

    k_all<<<GRID_TOTAL, 256>>>((const float4*)onehot,
                               (const float4*)centers,
                               (float4*)new_centers,
                               x, result);
}

// round 12
// speedup vs baseline: 1.0879x; 1.0879x over previous
#include <cuda_runtime.h>

#define NB 256
#define NC 50000
#define ND 512
#define ALPHA_F 0.5f

#define COPY_GROUPS 3125               // groups of 5 blocks: 4 copy + 1 find
#define GRID_MAIN  (COPY_GROUPS * 5)   // 15625

__device__ int g_labels[NB];

// ---------------------------------------------------------------- fused main pass (R9 code — at the BW wall)
// copy blocks (4 per group): 512 float4 each -> 12500 * 512 = NC*ND/4 exact
// find blocks (1 per group): 1024 float4 each -> 3125 * 1024 = NB*NC/4 exact
__global__ __launch_bounds__(256) void k_main(const float4* __restrict__ oh,
                                              const float4* __restrict__ centers,
                                              float4* __restrict__ out) {
    int g = blockIdx.x / 5;
    int r = blockIdx.x - g * 5;
    int t = threadIdx.x;

    if (r < 4) {
        int i = (g * 4 + r) * 512 + t;
        float4 a = __ldg(centers + i);
        float4 b = __ldg(centers + i + 256);
        __stcs(out + i, a);
        __stcs(out + i + 256, b);
    } else {
        int base = g * 1024 + t;
        float4 v0 = __ldcs(oh + base);
        float4 v1 = __ldcs(oh + base + 256);
        float4 v2 = __ldcs(oh + base + 512);
        float4 v3 = __ldcs(oh + base + 768);
        #pragma unroll
        for (int k = 0; k < 4; k++) {
            float4 w = (k == 0) ? v0 : (k == 1) ? v1 : (k == 2) ? v2 : v3;
            if (w.x != 0.0f || w.y != 0.0f || w.z != 0.0f || w.w != 0.0f) {
                int i = base + k * 256;
                int b = i / (NC / 4);
                int cb = (i - b * (NC / 4)) * 4;
                int off = (w.x != 0.0f) ? 0 : (w.y != 0.0f) ? 1 : (w.z != 0.0f) ? 2 : 3;
                g_labels[b] = cb + off;      // unique writer per sample row
            }
        }
    }
    // allow the dependent tail grid to begin launching early
    cudaTriggerProgrammaticLaunchCompletion();
}

// ---------------------------------------------------------------- tail (PDL): distance + fixup
// Launched with programmatic stream serialization: blocks start while k_main
// drains, preload x[b] (label-independent), then cudaGridDependencySynchronize()
// guarantees k_main completion + visibility before labels / out are touched.
__global__ __launch_bounds__(128) void k_tail(const float* __restrict__ x,
                                              const float* __restrict__ centers,
                                              float* __restrict__ out,
                                              float* __restrict__ result) {
    __shared__ int      s_lab[NB];
    __shared__ unsigned s_mask[8];
    __shared__ float    s_warp[4];
    int b = blockIdx.x;
    int t = threadIdx.x;
    int w = t >> 5, lane = t & 31;

    // label-independent prologue: overlap with k_main tail
    float4 xv = ((const float4*)(x + (size_t)b * ND))[t];

    cudaGridDependencySynchronize();     // k_main done + results visible

    s_lab[t]       = g_labels[t];
    s_lab[t + 128] = g_labels[t + 128];
    __syncthreads();

    int lab = s_lab[b];

    unsigned m0 = __ballot_sync(0xFFFFFFFFu, s_lab[t]       == lab);
    unsigned m1 = __ballot_sync(0xFFFFFFFFu, s_lab[t + 128] == lab);
    if (lane == 0) { s_mask[w] = m0; s_mask[w + 4] = m1; }

    float4 cv = ((const float4*)(centers + (size_t)lab * ND))[t];
    float dx = xv.x - cv.x, dy = xv.y - cv.y, dz = xv.z - cv.z, dw = xv.w - cv.w;
    float s = dx * dx + dy * dy + dz * dz + dw * dw;
    #pragma unroll
    for (int off = 16; off > 0; off >>= 1)
        s += __shfl_down_sync(0xFFFFFFFFu, s, off);
    if ((t & 31) == 0) s_warp[t >> 5] = s;
    __syncthreads();                     // covers s_warp AND s_mask
    if (t == 0)
        result[b] = s_warp[0] + s_warp[1] + s_warp[2] + s_warp[3];

    // ownership: first sample with this label does the row fixup
    int minidx = -1;
    #pragma unroll
    for (int i = 0; i < 8; i++) {
        unsigned m = s_mask[i];
        if (m) { minidx = i * 32 + __ffs(m) - 1; break; }
    }
    if (minidx != b) return;

    int cnt = 0;
    #pragma unroll
    for (int i = 0; i < 8; i++) cnt += __popc(s_mask[i]);

    float4 sum = make_float4(0.f, 0.f, 0.f, 0.f);
    #pragma unroll
    for (int i = 0; i < 8; i++) {
        unsigned m = s_mask[i];
        while (m) {
            int q = i * 32 + __ffs(m) - 1;   // increasing q: deterministic order
            m &= m - 1;
            float4 v = ((const float4*)(x + (size_t)q * ND))[t];
            sum.x += v.x; sum.y += v.y; sum.z += v.z; sum.w += v.w;
        }
    }

    float fc = (float)cnt;
    float inv = ALPHA_F / (fc + 1.0f);
    float scale = 1.0f - inv * fc;

    float4 o;
    o.x = cv.x * scale + inv * sum.x;
    o.y = cv.y * scale + inv * sum.y;
    o.z = cv.z * scale + inv * sum.z;
    o.w = cv.w * scale + inv * sum.w;
    ((float4*)(out + (size_t)lab * ND))[t] = o;
}

// ---------------------------------------------------------------- launch
extern "C" void kernel_launch(void* const* d_in, const int* in_sizes, int n_in,
                              void* d_out, int out_size) {
    const float* x       = (const float*)d_in[0];   // [256, 512]
    const float* onehot  = (const float*)d_in[1];   // [256, 50000]
    const float* centers = (const float*)d_in[2];   // [50000, 512]

    float* result      = (float*)d_out;             // [256]
    float* new_centers = (float*)d_out + NB;        // [50000, 512]

    k_main<<<GRID_MAIN, 256>>>((const float4*)onehot,
                               (const float4*)centers,
                               (float4*)new_centers);

    // dependent tail with programmatic (early) launch
    cudaLaunchAttribute attr[1];
    attr[0].id = cudaLaunchAttributeProgrammaticStreamSerialization;
    attr[0].val.programmaticStreamSerializationAllowed = 1;
    cudaLaunchConfig_t cfg = {};
    cfg.gridDim = dim3(NB, 1, 1);
    cfg.blockDim = dim3(128, 1, 1);
    cfg.dynamicSmemBytes = 0;
    cfg.stream = 0;
    cfg.attrs = attr;
    cfg.numAttrs = 1;
    cudaLaunchKernelEx(&cfg, k_tail, x, centers, new_centers, result);
}